// round 1
// baseline (speedup 1.0000x reference)
#include <cuda_runtime.h>

#define SIZE 28
#define TSTEPS 64
#define PITCH 32   // bank-conflict-free pitch for [t][c] layout

__global__ __launch_bounds__(256) void draw_image_kernel(
    const float* __restrict__ x,   // (B, T, 3)
    float* __restrict__ out)       // (B, SIZE, SIZE)
{
    __shared__ float s_px[TSTEPS * PITCH];   // exp(-(rng[c]-x_t)^2 * g)
    __shared__ float s_pyw[TSTEPS * PITCH];  // inten_t * exp(-(rng[r]-y_t)^2 * g)

    const int b = blockIdx.x;
    const int tid = threadIdx.x;
    const float* xb = x + (size_t)b * TSTEPS * 3;

    const float g = (SIZE * 0.5f) * (SIZE * 0.5f);  // (SIZE/2)^2 = 196
    const float inv_size = 1.0f / SIZE;

    // Precompute separable Gaussian factors for all 64 strokes.
    // 64*28 = 1792 entries each; 256 threads -> 7 iters.
    for (int i = tid; i < TSTEPS * SIZE; i += blockDim.x) {
        const int t = i / SIZE;
        const int c = i - t * SIZE;
        const float rng = (float)c * inv_size - 0.5f;

        const float sx = xb[t * 3 + 0];
        const float sy = xb[t * 3 + 1];
        const float si = xb[t * 3 + 2];

        const float dx = rng - sx;
        s_px[t * PITCH + c] = __expf(-dx * dx * g);

        const float dy = rng - sy;
        s_pyw[t * PITCH + c] = si * __expf(-dy * dy * g);
    }
    __syncthreads();

    // Each thread covers pixels p, p+256, ... (784 pixels total).
    float* outb = out + (size_t)b * SIZE * SIZE;
    for (int p = tid; p < SIZE * SIZE; p += blockDim.x) {
        const int r = p / SIZE;
        const int c = p - r * SIZE;
        float acc = 0.0f;
        #pragma unroll
        for (int t = 0; t < TSTEPS; t++) {
            acc = fmaxf(acc, s_pyw[t * PITCH + r] * s_px[t * PITCH + c]);
        }
        outb[p] = acc;
    }
}

extern "C" void kernel_launch(void* const* d_in, const int* in_sizes, int n_in,
                              void* d_out, int out_size)
{
    const float* x = (const float*)d_in[0];
    float* out = (float*)d_out;

    // B derived from input size: in_sizes[0] = B * T * 3
    const int B = in_sizes[0] / (TSTEPS * 3);

    draw_image_kernel<<<B, 256>>>(x, out);
}

// round 2
// speedup vs baseline: 1.5940x; 1.5940x over previous
#include <cuda_runtime.h>

#define SIZE 28
#define TSTEPS 64
#define PITCH 32        // floats per t-row in shared (bank/float4 friendly)
#define NTHREADS 224    // 7 warps; 196 active in mainloop; 1792/224 = 8 prologue iters

__global__ __launch_bounds__(NTHREADS) void draw_image_kernel(
    const float* __restrict__ x,   // (B, T, 3)
    float* __restrict__ out)       // (B, SIZE, SIZE)
{
    __shared__ float s_px[TSTEPS * PITCH];   // exp(-(rng[c]-x_t)^2 * g)
    __shared__ float s_pyw[TSTEPS * PITCH];  // inten_t * exp(-(rng[r]-y_t)^2 * g)

    const int b = blockIdx.x;
    const int tid = threadIdx.x;
    const float* xb = x + (size_t)b * TSTEPS * 3;

    const float g = (SIZE * 0.5f) * (SIZE * 0.5f);  // 196
    const float inv_size = 1.0f / SIZE;

    // Prologue: 64*28 = 1792 entries per table; 224 threads -> exactly 8 iters.
    #pragma unroll
    for (int it = 0; it < 8; it++) {
        const int i = tid + it * NTHREADS;
        const int t = i / SIZE;
        const int c = i - t * SIZE;
        const float rng = (float)c * inv_size - 0.5f;

        const float sx = xb[t * 3 + 0];
        const float sy = xb[t * 3 + 1];
        const float si = xb[t * 3 + 2];

        const float dx = rng - sx;
        s_px[t * PITCH + c] = __expf(-dx * dx * g);

        const float dy = rng - sy;
        s_pyw[t * PITCH + c] = si * __expf(-dy * dy * g);
    }
    __syncthreads();

    // Mainloop: 196 units = (colgroup cg in [0,7)) x (row r in [0,28)).
    // Lane layout cg = tid/28, r = tid%28: the float4 px load is a warp
    // broadcast; the pyw load hits 28 distinct banks. Both conflict-free.
    if (tid < 196) {
        const int cg = tid / SIZE;        // 0..6
        const int r  = tid - cg * SIZE;   // 0..27

        const float4* px4 = (const float4*)s_px;  // [t * (PITCH/4) + cg]

        float a0 = 0.0f, a1 = 0.0f, a2 = 0.0f, a3 = 0.0f;
        #pragma unroll
        for (int t = 0; t < TSTEPS; t++) {
            const float w  = s_pyw[t * PITCH + r];
            const float4 p = px4[t * (PITCH / 4) + cg];
            a0 = fmaxf(a0, w * p.x);
            a1 = fmaxf(a1, w * p.y);
            a2 = fmaxf(a2, w * p.z);
            a3 = fmaxf(a3, w * p.w);
        }

        // Byte offset = 112*r + 16*cg -> always 16B aligned: one STG.128.
        float* outp = out + (size_t)b * SIZE * SIZE + r * SIZE + cg * 4;
        *(float4*)outp = make_float4(a0, a1, a2, a3);
    }
}

extern "C" void kernel_launch(void* const* d_in, const int* in_sizes, int n_in,
                              void* d_out, int out_size)
{
    const float* x = (const float*)d_in[0];
    float* out = (float*)d_out;

    const int B = in_sizes[0] / (TSTEPS * 3);  // 1024

    draw_image_kernel<<<B, NTHREADS>>>(x, out);
}